// round 11
// baseline (speedup 1.0000x reference)
#include <cuda_runtime.h>
#include <cstdint>
#include <cstddef>

#define BMt 128
#define BNt 128
#define BKt 32
#define LDSP 36
#define TILEF (128*LDSP)
#define SMEMB (4*TILEF*4)

__device__ __align__(128) float g_Q [(size_t)96*1024*64];
__device__ __align__(128) float g_Ks[(size_t)96*1024*64];
__device__ __align__(128) float g_Kp[(size_t)96*1024*64];
__device__ __align__(128) float g_VT[(size_t)96*64*1024];
__device__ __align__(128) float g_A1[(size_t)96*1024*1024];
__device__ __align__(128) float g_A2[(size_t)96*1024*1024];
__device__ __align__(128) float g_M [(size_t)96*1024*1024];
__device__ __align__(128) float g_O [(size_t)8*1024*768];

__device__ __forceinline__ void cpa16(float* sdst, const float* gsrc, bool pred){
  uint32_t sa = (uint32_t)__cvta_generic_to_shared(sdst);
  int sz = pred ? 16 : 0;
  asm volatile("cp.async.cg.shared.global [%0], [%1], 16, %2;\n" :: "r"(sa), "l"(gsrc), "r"(sz));
}
__device__ __forceinline__ uint32_t f2tf(float f){
  uint32_t u; asm("cvt.rna.tf32.f32 %0, %1;" : "=r"(u) : "f"(f)); return u;
}
__device__ __forceinline__ void mma8(float* c, uint32_t a0,uint32_t a1,uint32_t a2,uint32_t a3,
                                     uint32_t b0,uint32_t b1){
  asm volatile("mma.sync.aligned.m16n8k8.row.col.f32.tf32.tf32.f32 "
               "{%0,%1,%2,%3},{%4,%5,%6,%7},{%8,%9},{%0,%1,%2,%3};\n"
    : "+f"(c[0]),"+f"(c[1]),"+f"(c[2]),"+f"(c[3])
    : "r"(a0),"r"(a1),"r"(a2),"r"(a3),"r"(b0),"r"(b1));
}

// C[z][m,n] = (sum_k A[z][m,k]*B[z][n,k] + bias[n]) * scale
// mode 0: plain C+z*cS, idx=m*N+n
// mode 1: head layout  ((b*12+h)*1024+s)*64+d   (m=b*1024+s, n=h*64+d)
// mode 2: head-T       ((b*12+h)*64+d)*1024+s
// mode 3: merge heads  (b*1024+m)*768 + h*64+n  (z=b*12+h)
__global__ void __launch_bounds__(256) gemm_tn(
    const float* __restrict__ Ag, const float* __restrict__ Bg,
    const float* __restrict__ bias, float* __restrict__ Cg,
    int M, int N, int K, size_t aS, size_t bS, size_t cS,
    float scale, int mode)
{
  extern __shared__ float smem[];
  const int z = blockIdx.z;
  Ag += (size_t)z * aS;  Bg += (size_t)z * bS;
  if (mode == 0) Cg += (size_t)z * cS;
  const int m0 = blockIdx.x * BMt, n0 = blockIdx.y * BNt;
  const int tid = threadIdx.x, lane = tid & 31, wid = tid >> 5;
  const int wm = wid >> 2, wn = wid & 3;

  float acc[4][4][4];
  #pragma unroll
  for (int i=0;i<4;i++)
    #pragma unroll
    for (int j=0;j<4;j++)
      #pragma unroll
      for (int q=0;q<4;q++) acc[i][j][q] = 0.f;

  const int lrow = tid >> 3;
  const int lcol = (tid & 7) << 2;

  { // prologue: tile 0 -> buf 0
    float* As = smem; float* Bs = smem + 2*TILEF;
    #pragma unroll
    for (int r=0;r<4;r++){
      int row = lrow + r*32;
      cpa16(As + row*LDSP + lcol, Ag + (size_t)(m0+row)*K + lcol, true);
      int nb = n0 + row;
      cpa16(Bs + row*LDSP + lcol, Bg + (size_t)nb*K + lcol, nb < N);
    }
    asm volatile("cp.async.commit_group;\n");
  }

  const int KT = K / BKt;
  for (int kt = 0; kt < KT; ++kt){
    if (kt + 1 < KT){
      int buf = (kt+1)&1; int k0 = (kt+1)*BKt;
      float* As = smem + buf*TILEF; float* Bs = smem + 2*TILEF + buf*TILEF;
      #pragma unroll
      for (int r=0;r<4;r++){
        int row = lrow + r*32;
        cpa16(As + row*LDSP + lcol, Ag + (size_t)(m0+row)*K + k0 + lcol, true);
        int nb = n0 + row;
        cpa16(Bs + row*LDSP + lcol, Bg + (size_t)nb*K + k0 + lcol, nb < N);
      }
      asm volatile("cp.async.commit_group;\n");
      asm volatile("cp.async.wait_group 1;\n");
    } else {
      asm volatile("cp.async.wait_group 0;\n");
    }
    __syncthreads();
    const float* As = smem + (kt&1)*TILEF;
    const float* Bs = smem + 2*TILEF + (kt&1)*TILEF;
    #pragma unroll
    for (int ks=0; ks<4; ++ks){
      const int kb = ks*8 + (lane&3);
      uint32_t af[4][4], bf[4][2];
      #pragma unroll
      for (int mi=0; mi<4; ++mi){
        int rb = wm*64 + mi*16 + (lane>>2);
        af[mi][0] = f2tf(As[rb*LDSP + kb]);
        af[mi][1] = f2tf(As[(rb+8)*LDSP + kb]);
        af[mi][2] = f2tf(As[rb*LDSP + kb + 4]);
        af[mi][3] = f2tf(As[(rb+8)*LDSP + kb + 4]);
      }
      #pragma unroll
      for (int ni=0; ni<4; ++ni){
        int nb = wn*32 + ni*8 + (lane>>2);
        bf[ni][0] = f2tf(Bs[nb*LDSP + kb]);
        bf[ni][1] = f2tf(Bs[nb*LDSP + kb + 4]);
      }
      #pragma unroll
      for (int mi=0; mi<4; ++mi)
        #pragma unroll
        for (int ni=0; ni<4; ++ni)
          mma8(acc[mi][ni], af[mi][0],af[mi][1],af[mi][2],af[mi][3],
               bf[ni][0],bf[ni][1]);
    }
    __syncthreads();
  }

  #pragma unroll
  for (int mi=0; mi<4; ++mi){
    #pragma unroll
    for (int ni=0; ni<4; ++ni){
      int r0 = m0 + wm*64 + mi*16 + (lane>>2);
      int c0 = n0 + wn*32 + ni*8 + ((lane&3)<<1);
      #pragma unroll
      for (int rr=0; rr<2; ++rr){
        int r = r0 + rr*8;
        #pragma unroll
        for (int cc=0; cc<2; ++cc){
          int c = c0 + cc;
          if (c >= N) continue;
          float v = acc[mi][ni][rr*2+cc];
          if (bias) v += bias[c];
          v *= scale;
          size_t idx;
          if (mode == 0) idx = (size_t)r * N + c;
          else if (mode == 1){ int b=r>>10, s=r&1023, h=c>>6, d=c&63;
            idx = (((size_t)b*12 + h)*1024 + s)*64 + d; }
          else if (mode == 2){ int b=r>>10, s=r&1023, h=c>>6, d=c&63;
            idx = (((size_t)b*12 + h)*64 + d)*1024 + s; }
          else { int b = z/12, h = z - b*12;
            idx = ((size_t)b*1024 + r)*768 + h*64 + c; }
          Cg[idx] = v;
        }
      }
    }
  }
}

__global__ void __launch_bounds__(256) row_softmax1024(float* __restrict__ X){
  const size_t row = blockIdx.x;
  float* r = X + (row << 10);
  const int t = threadIdx.x;
  float v[4]; float mx = -1e30f;
  #pragma unroll
  for (int i=0;i<4;i++){ v[i] = r[t + (i<<8)]; mx = fmaxf(mx, v[i]); }
  __shared__ float red[8], red2[8];
  #pragma unroll
  for (int o=16;o;o>>=1) mx = fmaxf(mx, __shfl_xor_sync(0xffffffffu, mx, o));
  if ((t&31)==0) red[t>>5] = mx;
  __syncthreads();
  float m = red[0];
  #pragma unroll
  for (int i=1;i<8;i++) m = fmaxf(m, red[i]);
  float s = 0.f;
  #pragma unroll
  for (int i=0;i<4;i++){ v[i] = __expf(v[i]-m); s += v[i]; }
  #pragma unroll
  for (int o=16;o;o>>=1) s += __shfl_xor_sync(0xffffffffu, s, o);
  if ((t&31)==0) red2[t>>5] = s;
  __syncthreads();
  float S = 0.f;
  #pragma unroll
  for (int i=0;i<8;i++) S += red2[i];
  float rc = 1.0f / S;
  #pragma unroll
  for (int i=0;i<4;i++) r[t + (i<<8)] = v[i] * rc;
}

extern "C" void kernel_launch(void* const* d_in, const int* in_sizes, int n_in,
                              void* d_out, int out_size){
  const float *l   =(const float*)d_in[0];
  const float *sp  =(const float*)d_in[1];
  const float *p   =(const float*)d_in[2];
  const float *Wq  =(const float*)d_in[3],  *bq  =(const float*)d_in[4];
  const float *Wksp=(const float*)d_in[5],  *bksp=(const float*)d_in[6];
  const float *Wkp =(const float*)d_in[7],  *bkp =(const float*)d_in[8];
  const float *Wvsp=(const float*)d_in[9],  *bvsp=(const float*)d_in[10];
  const float *Wo  =(const float*)d_in[13], *bo  =(const float*)d_in[14];
  float* out = (float*)d_out;

  float *Q,*Ks,*Kp,*VT,*A1,*A2,*Mm,*O;
  cudaGetSymbolAddress((void**)&Q,  g_Q);
  cudaGetSymbolAddress((void**)&Ks, g_Ks);
  cudaGetSymbolAddress((void**)&Kp, g_Kp);
  cudaGetSymbolAddress((void**)&VT, g_VT);
  cudaGetSymbolAddress((void**)&A1, g_A1);
  cudaGetSymbolAddress((void**)&A2, g_A2);
  cudaGetSymbolAddress((void**)&Mm, g_M);
  cudaGetSymbolAddress((void**)&O,  g_O);

  cudaFuncSetAttribute((const void*)gemm_tn,
                       cudaFuncAttributeMaxDynamicSharedMemorySize, SMEMB);

  const float sc = 0.125f;  // 64^-0.5
  dim3 th(256);
  dim3 gp(8192/128, 768/128, 1);
  // projections (scale applied to q,k,v as in reference)
  gemm_tn<<<gp, th, SMEMB>>>(l,  Wq,   bq,   Q,  8192,768,768, 0,0,0, sc, 1);
  gemm_tn<<<gp, th, SMEMB>>>(sp, Wksp, bksp, Ks, 8192,768,768, 0,0,0, sc, 1);
  gemm_tn<<<gp, th, SMEMB>>>(p,  Wkp,  bkp,  Kp, 8192,768,768, 0,0,0, sc, 1);
  gemm_tn<<<gp, th, SMEMB>>>(sp, Wvsp, bvsp, VT, 8192,768,768, 0,0,0, sc, 2);
  // logits, stored transposed: A1T[k,s] = <Ksp[k,:],Q[s,:]>, A2T[p,s]
  dim3 gq(1024/128, 1024/128, 96);
  gemm_tn<<<gq, th, SMEMB>>>(Ks, Q, nullptr, A1, 1024,1024,64,
                             65536,65536,1048576, 1.f, 0);
  gemm_tn<<<gq, th, SMEMB>>>(Kp, Q, nullptr, A2, 1024,1024,64,
                             65536,65536,1048576, 1.f, 0);
  // softmax over s (rows of transposed maps)
  row_softmax1024<<<96*1024, th>>>(A1);
  row_softmax1024<<<96*1024, th>>>(A2);
  // M[p,k] = sum_s A2T[p,s] * A1T[k,s]   (the 206-GFLOP GEMM)
  gemm_tn<<<gq, th, SMEMB>>>(A2, A1, nullptr, Mm, 1024,1024,1024,
                             1048576,1048576,1048576, 1.f, 0);
  // softmax over k
  row_softmax1024<<<96*1024, th>>>(Mm);
  // O[p,d] = sum_k M[p,k] * VT[d,k], merged-head output layout
  dim3 gv(1024/128, 1, 96);
  gemm_tn<<<gv, th, SMEMB>>>(Mm, VT, nullptr, O, 1024,64,1024,
                             1048576, 65536, 0, 1.f, 3);
  // final: out = O @ Wo^T + bo
  dim3 go(8192/128, 768/128, 1);
  gemm_tn<<<go, th, SMEMB>>>(O, Wo, bo, out, 8192,768,768, 0,0,0, 1.f, 0);
}

// round 14
// speedup vs baseline: 1.3156x; 1.3156x over previous
#include <cuda_runtime.h>
#include <cuda_bf16.h>
#include <cstdint>
#include <cstddef>

// ---------------- tf32 kernel config ----------------
#define BMt 128
#define BNt 128
#define BKt 32
#define LDSP 36
#define TILEF (128*LDSP)
#define SMEMB (4*TILEF*4)

// ---------------- bf16 kernel config ----------------
#define LDSB 40                 // bf16 elems per smem row (20 words -> conflict-free)
#define TILEB (128*LDSB)
#define SMEMB2 (4*TILEB*2)      // 40960 bytes (2-stage A+B)

// ---------------- scratch ----------------
__device__ __align__(128) __nv_bfloat16 g_Qb [(size_t)96*1024*64];
__device__ __align__(128) __nv_bfloat16 g_Ksb[(size_t)96*1024*64];
__device__ __align__(128) __nv_bfloat16 g_Kpb[(size_t)96*1024*64];
__device__ __align__(128) float         g_VT [(size_t)96*64*1024];
__device__ __align__(128) __nv_bfloat16 g_A1b[(size_t)96*1024*1024];
__device__ __align__(128) __nv_bfloat16 g_A2b[(size_t)96*1024*1024];
__device__ __align__(128) __nv_bfloat16 g_Mb [(size_t)96*1024*1024];  // M logits (bf16)
__device__ __align__(128) float         g_Mp [(size_t)96*1024*1024];  // M probs (fp32)
__device__ __align__(128) float         g_O  [(size_t)8*1024*768];

// ---------------- helpers ----------------
__device__ __forceinline__ void cpa16(float* sdst, const float* gsrc, bool pred){
  uint32_t sa = (uint32_t)__cvta_generic_to_shared(sdst);
  int sz = pred ? 16 : 0;
  asm volatile("cp.async.cg.shared.global [%0], [%1], 16, %2;\n" :: "r"(sa), "l"(gsrc), "r"(sz));
}
__device__ __forceinline__ void cpa16b(__nv_bfloat16* sdst, const __nv_bfloat16* gsrc, bool pred){
  uint32_t sa = (uint32_t)__cvta_generic_to_shared(sdst);
  int sz = pred ? 16 : 0;
  asm volatile("cp.async.cg.shared.global [%0], [%1], 16, %2;\n" :: "r"(sa), "l"(gsrc), "r"(sz));
}
__device__ __forceinline__ uint32_t f2tf(float f){
  uint32_t u; asm("cvt.rna.tf32.f32 %0, %1;" : "=r"(u) : "f"(f)); return u;
}
__device__ __forceinline__ void mma8(float* c, uint32_t a0,uint32_t a1,uint32_t a2,uint32_t a3,
                                     uint32_t b0,uint32_t b1){
  asm volatile("mma.sync.aligned.m16n8k8.row.col.f32.tf32.tf32.f32 "
               "{%0,%1,%2,%3},{%4,%5,%6,%7},{%8,%9},{%0,%1,%2,%3};\n"
    : "+f"(c[0]),"+f"(c[1]),"+f"(c[2]),"+f"(c[3])
    : "r"(a0),"r"(a1),"r"(a2),"r"(a3),"r"(b0),"r"(b1));
}
__device__ __forceinline__ void mma16(float* c, uint32_t a0,uint32_t a1,uint32_t a2,uint32_t a3,
                                      uint32_t b0,uint32_t b1){
  asm volatile("mma.sync.aligned.m16n8k16.row.col.f32.bf16.bf16.f32 "
               "{%0,%1,%2,%3},{%4,%5,%6,%7},{%8,%9},{%0,%1,%2,%3};\n"
    : "+f"(c[0]),"+f"(c[1]),"+f"(c[2]),"+f"(c[3])
    : "r"(a0),"r"(a1),"r"(a2),"r"(a3),"r"(b0),"r"(b1));
}

// ================= tf32 TN GEMM =================
// C[z][m,n] = (sum_k A[z][m,k]*B[z][n,k] + bias[n]) * scale
// mode 0: fp32 plain  C+z*cS, idx=m*N+n
// mode 2: fp32 head-T ((b*12+h)*64+d)*1024+s      (m=b*1024+s, n=h*64+d)
// mode 3: fp32 merge-heads: z=b*12+h, idx=(b*1024+m)*768 + h*64 + n
// mode 4: bf16 head   ((b*12+h)*1024+s)*64+d
__global__ void __launch_bounds__(256) gemm_tn(
    const float* __restrict__ Ag, const float* __restrict__ Bg,
    const float* __restrict__ bias, void* __restrict__ Cgv,
    int M, int N, int K, size_t aS, size_t bS, size_t cS,
    float scale, int mode)
{
  extern __shared__ float smem[];
  const int z = blockIdx.z;
  Ag += (size_t)z * aS;  Bg += (size_t)z * bS;
  const int m0 = blockIdx.x * BMt, n0 = blockIdx.y * BNt;
  const int tid = threadIdx.x, lane = tid & 31, wid = tid >> 5;
  const int wm = wid >> 2, wn = wid & 3;

  float acc[4][4][4];
  #pragma unroll
  for (int i=0;i<4;i++)
    #pragma unroll
    for (int j=0;j<4;j++)
      #pragma unroll
      for (int q=0;q<4;q++) acc[i][j][q] = 0.f;

  const int lrow = tid >> 3;
  const int lcol = (tid & 7) << 2;

  {
    float* As = smem; float* Bs = smem + 2*TILEF;
    #pragma unroll
    for (int r=0;r<4;r++){
      int row = lrow + r*32;
      cpa16(As + row*LDSP + lcol, Ag + (size_t)(m0+row)*K + lcol, true);
      int nb = n0 + row;
      cpa16(Bs + row*LDSP + lcol, Bg + (size_t)nb*K + lcol, nb < N);
    }
    asm volatile("cp.async.commit_group;\n");
  }

  const int KT = K / BKt;
  for (int kt = 0; kt < KT; ++kt){
    if (kt + 1 < KT){
      int buf = (kt+1)&1; int k0 = (kt+1)*BKt;
      float* As = smem + buf*TILEF; float* Bs = smem + 2*TILEF + buf*TILEF;
      #pragma unroll
      for (int r=0;r<4;r++){
        int row = lrow + r*32;
        cpa16(As + row*LDSP + lcol, Ag + (size_t)(m0+row)*K + k0 + lcol, true);
        int nb = n0 + row;
        cpa16(Bs + row*LDSP + lcol, Bg + (size_t)nb*K + k0 + lcol, nb < N);
      }
      asm volatile("cp.async.commit_group;\n");
      asm volatile("cp.async.wait_group 1;\n");
    } else {
      asm volatile("cp.async.wait_group 0;\n");
    }
    __syncthreads();
    const float* As = smem + (kt&1)*TILEF;
    const float* Bs = smem + 2*TILEF + (kt&1)*TILEF;
    #pragma unroll
    for (int ks=0; ks<4; ++ks){
      const int kb = ks*8 + (lane&3);
      uint32_t af[4][4], bfv[4][2];
      #pragma unroll
      for (int mi=0; mi<4; ++mi){
        int rb = wm*64 + mi*16 + (lane>>2);
        af[mi][0] = f2tf(As[rb*LDSP + kb]);
        af[mi][1] = f2tf(As[(rb+8)*LDSP + kb]);
        af[mi][2] = f2tf(As[rb*LDSP + kb + 4]);
        af[mi][3] = f2tf(As[(rb+8)*LDSP + kb + 4]);
      }
      #pragma unroll
      for (int ni=0; ni<4; ++ni){
        int nb = wn*32 + ni*8 + (lane>>2);
        bfv[ni][0] = f2tf(Bs[nb*LDSP + kb]);
        bfv[ni][1] = f2tf(Bs[nb*LDSP + kb + 4]);
      }
      #pragma unroll
      for (int mi=0; mi<4; ++mi)
        #pragma unroll
        for (int ni=0; ni<4; ++ni)
          mma8(acc[mi][ni], af[mi][0],af[mi][1],af[mi][2],af[mi][3],
               bfv[ni][0],bfv[ni][1]);
    }
    __syncthreads();
  }

  #pragma unroll
  for (int mi=0; mi<4; ++mi){
    #pragma unroll
    for (int ni=0; ni<4; ++ni){
      int r0 = m0 + wm*64 + mi*16 + (lane>>2);
      int c0 = n0 + wn*32 + ni*8 + ((lane&3)<<1);
      #pragma unroll
      for (int rr=0; rr<2; ++rr){
        int r = r0 + rr*8;
        #pragma unroll
        for (int cc=0; cc<2; ++cc){
          int c = c0 + cc;
          if (c >= N) continue;
          float v = acc[mi][ni][rr*2+cc];
          if (bias) v += bias[c];
          v *= scale;
          if (mode == 0){
            ((float*)Cgv)[(size_t)z*cS + (size_t)r*N + c] = v;
          } else if (mode == 3){
            int b = z/12, h = z - b*12;
            ((float*)Cgv)[((size_t)b*1024 + r)*768 + h*64 + c] = v;
          } else {
            int b=r>>10, s=r&1023, h=c>>6, d=c&63;
            if (mode == 4)
              ((__nv_bfloat16*)Cgv)[(((size_t)b*12 + h)*1024 + s)*64 + d] = __float2bfloat16(v);
            else // mode 2
              ((float*)Cgv)[(((size_t)b*12 + h)*64 + d)*1024 + s] = v;
          }
        }
      }
    }
  }
}

// ================= bf16 TN GEMM (attention path) =================
// C[z][m,n] = sum_k A[z][m,k]*B[z][n,k]  -> bf16 plain (C + z*cS)
__global__ void __launch_bounds__(256,2) gemm_bf16_tn(
    const __nv_bfloat16* __restrict__ Ag, const __nv_bfloat16* __restrict__ Bg,
    __nv_bfloat16* __restrict__ Cg, int M, int N, int K,
    size_t aS, size_t bS, size_t cS)
{
  extern __shared__ __nv_bfloat16 smb[];
  const int z = blockIdx.z;
  Ag += (size_t)z*aS;  Bg += (size_t)z*bS;  Cg += (size_t)z*cS;
  const int m0 = blockIdx.x*128, n0 = blockIdx.y*128;
  const int tid = threadIdx.x, lane = tid&31, wid = tid>>5;
  const int wm = wid>>2, wn = wid&3;

  float acc[4][4][4];
  #pragma unroll
  for (int i=0;i<4;i++)
    #pragma unroll
    for (int j=0;j<4;j++)
      #pragma unroll
      for (int q=0;q<4;q++) acc[i][j][q] = 0.f;

  const int lrow = tid >> 2;        // 0..63
  const int lch  = (tid & 3) * 8;   // bf16 chunk col: 0,8,16,24  (full 32 covered)

  { // prologue -> buf 0
    __nv_bfloat16* As = smb; __nv_bfloat16* Bs = smb + 2*TILEB;
    #pragma unroll
    for (int r=0;r<2;r++){
      int row = lrow + r*64;
      cpa16b(As + row*LDSB + lch, Ag + (size_t)(m0+row)*K + lch, true);
      int nb = n0 + row;
      cpa16b(Bs + row*LDSB + lch, Bg + (size_t)nb*K + lch, nb < N);
    }
    asm volatile("cp.async.commit_group;\n");
  }

  const int KT = K / 32;
  for (int kt = 0; kt < KT; ++kt){
    if (kt + 1 < KT){
      int buf = (kt+1)&1; int k0 = (kt+1)*32;
      __nv_bfloat16* As = smb + buf*TILEB; __nv_bfloat16* Bs = smb + 2*TILEB + buf*TILEB;
      #pragma unroll
      for (int r=0;r<2;r++){
        int row = lrow + r*64;
        cpa16b(As + row*LDSB + lch, Ag + (size_t)(m0+row)*K + k0 + lch, true);
        int nb = n0 + row;
        cpa16b(Bs + row*LDSB + lch, Bg + (size_t)nb*K + k0 + lch, nb < N);
      }
      asm volatile("cp.async.commit_group;\n");
      asm volatile("cp.async.wait_group 1;\n");
    } else {
      asm volatile("cp.async.wait_group 0;\n");
    }
    __syncthreads();
    const uint32_t* Aw = (const uint32_t*)(smb + (kt&1)*TILEB);
    const uint32_t* Bw = (const uint32_t*)(smb + 2*TILEB + (kt&1)*TILEB);
    #pragma unroll
    for (int ks=0; ks<2; ++ks){
      const int kw = ks*8 + (lane&3);
      uint32_t af[4][4], bfv[4][2];
      #pragma unroll
      for (int mi=0; mi<4; ++mi){
        int rb = wm*64 + mi*16 + (lane>>2);
        af[mi][0] = Aw[rb*20 + kw];
        af[mi][1] = Aw[(rb+8)*20 + kw];
        af[mi][2] = Aw[rb*20 + kw + 4];
        af[mi][3] = Aw[(rb+8)*20 + kw + 4];
      }
      #pragma unroll
      for (int ni=0; ni<4; ++ni){
        int nb = wn*32 + ni*8 + (lane>>2);
        bfv[ni][0] = Bw[nb*20 + kw];
        bfv[ni][1] = Bw[nb*20 + kw + 4];
      }
      #pragma unroll
      for (int mi=0; mi<4; ++mi)
        #pragma unroll
        for (int ni=0; ni<4; ++ni)
          mma16(acc[mi][ni], af[mi][0],af[mi][1],af[mi][2],af[mi][3],
                bfv[ni][0],bfv[ni][1]);
    }
    __syncthreads();
  }

  #pragma unroll
  for (int mi=0; mi<4; ++mi){
    #pragma unroll
    for (int ni=0; ni<4; ++ni){
      int r0 = m0 + wm*64 + mi*16 + (lane>>2);
      int c0 = n0 + wn*32 + ni*8 + ((lane&3)<<1);
      #pragma unroll
      for (int rr=0; rr<2; ++rr){
        int r = r0 + rr*8;
        #pragma unroll
        for (int cc=0; cc<2; ++cc){
          int c = c0 + cc;
          if (c >= N) continue;
          Cg[(size_t)r*N + c] = __float2bfloat16(acc[mi][ni][rr*2+cc]);
        }
      }
    }
  }
}

// ================= softmaxes =================
__global__ void __launch_bounds__(256) row_softmax1024_bf16(__nv_bfloat16* __restrict__ X){
  const size_t row = blockIdx.x;
  __nv_bfloat16* r = X + (row << 10);
  const int t = threadIdx.x;
  float v[4]; float mx = -1e30f;
  #pragma unroll
  for (int i=0;i<4;i++){ v[i] = __bfloat162float(r[t + (i<<8)]); mx = fmaxf(mx, v[i]); }
  __shared__ float red[8], red2[8];
  #pragma unroll
  for (int o=16;o;o>>=1) mx = fmaxf(mx, __shfl_xor_sync(0xffffffffu, mx, o));
  if ((t&31)==0) red[t>>5] = mx;
  __syncthreads();
  float m = red[0];
  #pragma unroll
  for (int i=1;i<8;i++) m = fmaxf(m, red[i]);
  float s = 0.f;
  #pragma unroll
  for (int i=0;i<4;i++){ v[i] = __expf(v[i]-m); s += v[i]; }
  #pragma unroll
  for (int o=16;o;o>>=1) s += __shfl_xor_sync(0xffffffffu, s, o);
  if ((t&31)==0) red2[t>>5] = s;
  __syncthreads();
  float S = 0.f;
  #pragma unroll
  for (int i=0;i<8;i++) S += red2[i];
  float rc = 1.0f / S;
  #pragma unroll
  for (int i=0;i<4;i++) r[t + (i<<8)] = __float2bfloat16(v[i] * rc);
}

// reads bf16 logits, writes fp32 probabilities (direct path: no bf16 quantization)
__global__ void __launch_bounds__(256) row_softmax1024_b2f(
    const __nv_bfloat16* __restrict__ X, float* __restrict__ Y){
  const size_t row = blockIdx.x;
  const __nv_bfloat16* r = X + (row << 10);
  float* w = Y + (row << 10);
  const int t = threadIdx.x;
  float v[4]; float mx = -1e30f;
  #pragma unroll
  for (int i=0;i<4;i++){ v[i] = __bfloat162float(r[t + (i<<8)]); mx = fmaxf(mx, v[i]); }
  __shared__ float red[8], red2[8];
  #pragma unroll
  for (int o=16;o;o>>=1) mx = fmaxf(mx, __shfl_xor_sync(0xffffffffu, mx, o));
  if ((t&31)==0) red[t>>5] = mx;
  __syncthreads();
  float m = red[0];
  #pragma unroll
  for (int i=1;i<8;i++) m = fmaxf(m, red[i]);
  float s = 0.f;
  #pragma unroll
  for (int i=0;i<4;i++){ v[i] = __expf(v[i]-m); s += v[i]; }
  #pragma unroll
  for (int o=16;o;o>>=1) s += __shfl_xor_sync(0xffffffffu, s, o);
  if ((t&31)==0) red2[t>>5] = s;
  __syncthreads();
  float S = 0.f;
  #pragma unroll
  for (int i=0;i<8;i++) S += red2[i];
  float rc = 1.0f / S;
  #pragma unroll
  for (int i=0;i<4;i++) w[t + (i<<8)] = v[i] * rc;
}

extern "C" void kernel_launch(void* const* d_in, const int* in_sizes, int n_in,
                              void* d_out, int out_size){
  const float *l   =(const float*)d_in[0];
  const float *sp  =(const float*)d_in[1];
  const float *p   =(const float*)d_in[2];
  const float *Wq  =(const float*)d_in[3],  *bq  =(const float*)d_in[4];
  const float *Wksp=(const float*)d_in[5],  *bksp=(const float*)d_in[6];
  const float *Wkp =(const float*)d_in[7],  *bkp =(const float*)d_in[8];
  const float *Wvsp=(const float*)d_in[9],  *bvsp=(const float*)d_in[10];
  const float *Wo  =(const float*)d_in[13], *bo  =(const float*)d_in[14];
  float* out = (float*)d_out;

  __nv_bfloat16 *Q,*Ks,*Kp,*A1,*A2,*Mm;
  float *VT,*Mp,*O;
  cudaGetSymbolAddress((void**)&Q,  g_Qb);
  cudaGetSymbolAddress((void**)&Ks, g_Ksb);
  cudaGetSymbolAddress((void**)&Kp, g_Kpb);
  cudaGetSymbolAddress((void**)&VT, g_VT);
  cudaGetSymbolAddress((void**)&A1, g_A1b);
  cudaGetSymbolAddress((void**)&A2, g_A2b);
  cudaGetSymbolAddress((void**)&Mm, g_Mb);
  cudaGetSymbolAddress((void**)&Mp, g_Mp);
  cudaGetSymbolAddress((void**)&O,  g_O);

  cudaFuncSetAttribute((const void*)gemm_tn,
                       cudaFuncAttributeMaxDynamicSharedMemorySize, SMEMB);
  cudaFuncSetAttribute((const void*)gemm_bf16_tn,
                       cudaFuncAttributeMaxDynamicSharedMemorySize, SMEMB2);

  const float sc = 0.125f;  // 64^-0.5
  dim3 th(256);

  // projections (tf32): Q/K bf16 head layout, V fp32 head-T (direct path)
  dim3 gp(8192/128, 768/128, 1);
  gemm_tn<<<gp, th, SMEMB>>>(l,  Wq,   bq,   Q,  8192,768,768, 0,0,0, sc, 4);
  gemm_tn<<<gp, th, SMEMB>>>(sp, Wksp, bksp, Ks, 8192,768,768, 0,0,0, sc, 4);
  gemm_tn<<<gp, th, SMEMB>>>(p,  Wkp,  bkp,  Kp, 8192,768,768, 0,0,0, sc, 4);
  gemm_tn<<<gp, th, SMEMB>>>(sp, Wvsp, bvsp, VT, 8192,768,768, 0,0,0, sc, 2);

  // logits transposed (bf16): A1T[k,s] = <Ksp[k,:],Q[s,:]>, A2T[p,s]
  dim3 gq(1024/128, 1024/128, 96);
  gemm_bf16_tn<<<gq, th, SMEMB2>>>(Ks, Q, A1, 1024,1024,64, 65536,65536,1048576);
  gemm_bf16_tn<<<gq, th, SMEMB2>>>(Kp, Q, A2, 1024,1024,64, 65536,65536,1048576);

  // softmax over s (rows of transposed maps), bf16 in/out (damped path)
  row_softmax1024_bf16<<<96*1024, th>>>(A1);
  row_softmax1024_bf16<<<96*1024, th>>>(A2);

  // M[p,k] = sum_s A2T[p,s] * A1T[k,s]  (206 GFLOP, bf16)
  gemm_bf16_tn<<<gq, th, SMEMB2>>>(A2, A1, Mm, 1024,1024,1024,
                                   1048576,1048576,1048576);

  // softmax over k: bf16 logits -> fp32 probs (direct path needs fp32)
  row_softmax1024_b2f<<<96*1024, th>>>(Mm, Mp);

  // O[p,d] = sum_k Mp[p,k] * VT[d,k]  (tf32, fp32 in/out, merged heads)
  dim3 gv(1024/128, 1, 96);
  gemm_tn<<<gv, th, SMEMB>>>(Mp, VT, nullptr, O, 1024,64,1024,
                             1048576, 65536, 0, 1.f, 3);

  // final: out = O @ Wo^T + bo  (tf32, fp32 out)
  dim3 go(8192/128, 768/128, 1);
  gemm_tn<<<go, th, SMEMB>>>(O, Wo, bo, out, 8192,768,768, 0,0,0, 1.f, 0);
}

// round 15
// speedup vs baseline: 1.4893x; 1.1320x over previous
#include <cuda_runtime.h>
#include <cuda_bf16.h>
#include <cstdint>
#include <cstddef>

// ---------------- tf32 kernel config ----------------
#define LDSP 36
#define TILEF (128*LDSP)

// ---------------- bf16 kernel config ----------------
#define LDSB 40
#define TILEB (128*LDSB)
#define SMEMB2 (4*TILEB*2)      // 40960 bytes

// ---------------- scratch ----------------
__device__ __align__(128) __nv_bfloat16 g_Qb [(size_t)96*1024*64];
__device__ __align__(128) __nv_bfloat16 g_Ksb[(size_t)96*1024*64];
__device__ __align__(128) __nv_bfloat16 g_Kpb[(size_t)96*1024*64];
__device__ __align__(128) float         g_VT [(size_t)96*64*1024];
__device__ __align__(128) __nv_bfloat16 g_A1b[(size_t)96*1024*1024];
__device__ __align__(128) __nv_bfloat16 g_A2b[(size_t)96*1024*1024];
__device__ __align__(128) __nv_bfloat16 g_Mb [(size_t)96*1024*1024];
__device__ __align__(128) float         g_Mp [(size_t)96*1024*1024];
__device__ __align__(128) float         g_O  [(size_t)8*1024*768];

// ---------------- helpers ----------------
__device__ __forceinline__ void cpa16(float* sdst, const float* gsrc, bool pred){
  uint32_t sa = (uint32_t)__cvta_generic_to_shared(sdst);
  int sz = pred ? 16 : 0;
  asm volatile("cp.async.cg.shared.global [%0], [%1], 16, %2;\n" :: "r"(sa), "l"(gsrc), "r"(sz));
}
__device__ __forceinline__ void cpa16b(__nv_bfloat16* sdst, const __nv_bfloat16* gsrc, bool pred){
  uint32_t sa = (uint32_t)__cvta_generic_to_shared(sdst);
  int sz = pred ? 16 : 0;
  asm volatile("cp.async.cg.shared.global [%0], [%1], 16, %2;\n" :: "r"(sa), "l"(gsrc), "r"(sz));
}
__device__ __forceinline__ uint32_t f2tf(float f){
  uint32_t u; asm("cvt.rna.tf32.f32 %0, %1;" : "=r"(u) : "f"(f)); return u;
}
__device__ __forceinline__ void mma8(float* c, uint32_t a0,uint32_t a1,uint32_t a2,uint32_t a3,
                                     uint32_t b0,uint32_t b1){
  asm volatile("mma.sync.aligned.m16n8k8.row.col.f32.tf32.tf32.f32 "
               "{%0,%1,%2,%3},{%4,%5,%6,%7},{%8,%9},{%0,%1,%2,%3};\n"
    : "+f"(c[0]),"+f"(c[1]),"+f"(c[2]),"+f"(c[3])
    : "r"(a0),"r"(a1),"r"(a2),"r"(a3),"r"(b0),"r"(b1));
}
__device__ __forceinline__ void mma16(float* c, uint32_t a0,uint32_t a1,uint32_t a2,uint32_t a3,
                                      uint32_t b0,uint32_t b1){
  asm volatile("mma.sync.aligned.m16n8k16.row.col.f32.bf16.bf16.f32 "
               "{%0,%1,%2,%3},{%4,%5,%6,%7},{%8,%9},{%0,%1,%2,%3};\n"
    : "+f"(c[0]),"+f"(c[1]),"+f"(c[2]),"+f"(c[3])
    : "r"(a0),"r"(a1),"r"(a2),"r"(a3),"r"(b0),"r"(b1));
}

// ================= tf32 TN GEMM, templated on BN =================
// C[z][m,n] = (sum_k A[z][m,k]*B[z][n,k] + bias[n]) * scale
// mode 0: fp32 plain  C+z*cS, idx=m*N+n
// mode 2: fp32 head-T ((b*12+h)*64+d)*1024+s      (m=b*1024+s, n=h*64+d)
// mode 3: fp32 merge-heads: z=b*12+h, idx=(b*1024+m)*768 + h*64 + n
// mode 4: bf16 head   ((b*12+h)*1024+s)*64+d
template<int BN>
__global__ void __launch_bounds__(256,2) gemm_tn(
    const float* __restrict__ Ag, const float* __restrict__ Bg,
    const float* __restrict__ bias, void* __restrict__ Cgv,
    int M, int N, int K, size_t aS, size_t bS, size_t cS,
    float scale, int mode)
{
  constexpr int WN = (BN == 128) ? 4 : 2;   // warps along N
  constexpr int WM = 8 / WN;                // warps along M
  constexpr int RM = 128 / WM;              // rows per warp
  constexpr int MI = RM / 16;               // 4 or 2
  constexpr int BTIL = BN * LDSP;

  extern __shared__ float smem[];
  const int z = blockIdx.z;
  Ag += (size_t)z * aS;  Bg += (size_t)z * bS;
  const int m0 = blockIdx.x * 128, n0 = blockIdx.y * BN;
  const int tid = threadIdx.x, lane = tid & 31, wid = tid >> 5;
  const int wm = wid / WN, wn = wid % WN;

  float acc[MI][4][4];
  #pragma unroll
  for (int i=0;i<MI;i++)
    #pragma unroll
    for (int j=0;j<4;j++)
      #pragma unroll
      for (int q=0;q<4;q++) acc[i][j][q] = 0.f;

  const int lrow = tid >> 3;
  const int lcol = (tid & 7) << 2;

  {
    float* As = smem; float* Bs = smem + 2*TILEF;
    #pragma unroll
    for (int r=0;r<4;r++){
      int row = lrow + r*32;
      cpa16(As + row*LDSP + lcol, Ag + (size_t)(m0+row)*K + lcol, true);
      if (row < BN){
        int nb = n0 + row;
        cpa16(Bs + row*LDSP + lcol, Bg + (size_t)nb*K + lcol, nb < N);
      }
    }
    asm volatile("cp.async.commit_group;\n");
  }

  const int KT = K / 32;
  for (int kt = 0; kt < KT; ++kt){
    if (kt + 1 < KT){
      int buf = (kt+1)&1; int k0 = (kt+1)*32;
      float* As = smem + buf*TILEF; float* Bs = smem + 2*TILEF + buf*BTIL;
      #pragma unroll
      for (int r=0;r<4;r++){
        int row = lrow + r*32;
        cpa16(As + row*LDSP + lcol, Ag + (size_t)(m0+row)*K + k0 + lcol, true);
        if (row < BN){
          int nb = n0 + row;
          cpa16(Bs + row*LDSP + lcol, Bg + (size_t)nb*K + k0 + lcol, nb < N);
        }
      }
      asm volatile("cp.async.commit_group;\n");
      asm volatile("cp.async.wait_group 1;\n");
    } else {
      asm volatile("cp.async.wait_group 0;\n");
    }
    __syncthreads();
    const float* As = smem + (kt&1)*TILEF;
    const float* Bs = smem + 2*TILEF + (kt&1)*BTIL;
    #pragma unroll
    for (int ks=0; ks<4; ++ks){
      const int kb = ks*8 + (lane&3);
      uint32_t af[MI][4], bfv[4][2];
      #pragma unroll
      for (int mi=0; mi<MI; ++mi){
        int rb = wm*RM + mi*16 + (lane>>2);
        af[mi][0] = f2tf(As[rb*LDSP + kb]);
        af[mi][1] = f2tf(As[(rb+8)*LDSP + kb]);
        af[mi][2] = f2tf(As[rb*LDSP + kb + 4]);
        af[mi][3] = f2tf(As[(rb+8)*LDSP + kb + 4]);
      }
      #pragma unroll
      for (int ni=0; ni<4; ++ni){
        int nb = wn*32 + ni*8 + (lane>>2);
        bfv[ni][0] = f2tf(Bs[nb*LDSP + kb]);
        bfv[ni][1] = f2tf(Bs[nb*LDSP + kb + 4]);
      }
      #pragma unroll
      for (int mi=0; mi<MI; ++mi)
        #pragma unroll
        for (int ni=0; ni<4; ++ni)
          mma8(acc[mi][ni], af[mi][0],af[mi][1],af[mi][2],af[mi][3],
               bfv[ni][0],bfv[ni][1]);
    }
    __syncthreads();
  }

  #pragma unroll
  for (int mi=0; mi<MI; ++mi){
    #pragma unroll
    for (int ni=0; ni<4; ++ni){
      int r0 = m0 + wm*RM + mi*16 + (lane>>2);
      int c0 = n0 + wn*32 + ni*8 + ((lane&3)<<1);
      #pragma unroll
      for (int rr=0; rr<2; ++rr){
        int r = r0 + rr*8;
        #pragma unroll
        for (int cc=0; cc<2; ++cc){
          int c = c0 + cc;
          if (c >= N) continue;
          float v = acc[mi][ni][rr*2+cc];
          if (bias) v += bias[c];
          v *= scale;
          if (mode == 0){
            ((float*)Cgv)[(size_t)z*cS + (size_t)r*N + c] = v;
          } else if (mode == 3){
            int b = z/12, h = z - b*12;
            ((float*)Cgv)[((size_t)b*1024 + r)*768 + h*64 + c] = v;
          } else {
            int b=r>>10, s=r&1023, h=c>>6, d=c&63;
            if (mode == 4)
              ((__nv_bfloat16*)Cgv)[(((size_t)b*12 + h)*1024 + s)*64 + d] = __float2bfloat16(v);
            else // mode 2
              ((float*)Cgv)[(((size_t)b*12 + h)*64 + d)*1024 + s] = v;
          }
        }
      }
    }
  }
}

// ================= bf16 TN GEMM (attention path) =================
__global__ void __launch_bounds__(256,2) gemm_bf16_tn(
    const __nv_bfloat16* __restrict__ Ag, const __nv_bfloat16* __restrict__ Bg,
    __nv_bfloat16* __restrict__ Cg, int M, int N, int K,
    size_t aS, size_t bS, size_t cS)
{
  extern __shared__ __nv_bfloat16 smb[];
  const int z = blockIdx.z;
  Ag += (size_t)z*aS;  Bg += (size_t)z*bS;  Cg += (size_t)z*cS;
  const int m0 = blockIdx.x*128, n0 = blockIdx.y*128;
  const int tid = threadIdx.x, lane = tid&31, wid = tid>>5;
  const int wm = wid>>2, wn = wid&3;

  float acc[4][4][4];
  #pragma unroll
  for (int i=0;i<4;i++)
    #pragma unroll
    for (int j=0;j<4;j++)
      #pragma unroll
      for (int q=0;q<4;q++) acc[i][j][q] = 0.f;

  const int lrow = tid >> 2;
  const int lch  = (tid & 3) * 8;

  {
    __nv_bfloat16* As = smb; __nv_bfloat16* Bs = smb + 2*TILEB;
    #pragma unroll
    for (int r=0;r<2;r++){
      int row = lrow + r*64;
      cpa16b(As + row*LDSB + lch, Ag + (size_t)(m0+row)*K + lch, true);
      int nb = n0 + row;
      cpa16b(Bs + row*LDSB + lch, Bg + (size_t)nb*K + lch, nb < N);
    }
    asm volatile("cp.async.commit_group;\n");
  }

  const int KT = K / 32;
  for (int kt = 0; kt < KT; ++kt){
    if (kt + 1 < KT){
      int buf = (kt+1)&1; int k0 = (kt+1)*32;
      __nv_bfloat16* As = smb + buf*TILEB; __nv_bfloat16* Bs = smb + 2*TILEB + buf*TILEB;
      #pragma unroll
      for (int r=0;r<2;r++){
        int row = lrow + r*64;
        cpa16b(As + row*LDSB + lch, Ag + (size_t)(m0+row)*K + k0 + lch, true);
        int nb = n0 + row;
        cpa16b(Bs + row*LDSB + lch, Bg + (size_t)nb*K + k0 + lch, nb < N);
      }
      asm volatile("cp.async.commit_group;\n");
      asm volatile("cp.async.wait_group 1;\n");
    } else {
      asm volatile("cp.async.wait_group 0;\n");
    }
    __syncthreads();
    const uint32_t* Aw = (const uint32_t*)(smb + (kt&1)*TILEB);
    const uint32_t* Bw = (const uint32_t*)(smb + 2*TILEB + (kt&1)*TILEB);
    #pragma unroll
    for (int ks=0; ks<2; ++ks){
      const int kw = ks*8 + (lane&3);
      uint32_t af[4][4], bfv[4][2];
      #pragma unroll
      for (int mi=0; mi<4; ++mi){
        int rb = wm*64 + mi*16 + (lane>>2);
        af[mi][0] = Aw[rb*20 + kw];
        af[mi][1] = Aw[(rb+8)*20 + kw];
        af[mi][2] = Aw[rb*20 + kw + 4];
        af[mi][3] = Aw[(rb+8)*20 + kw + 4];
      }
      #pragma unroll
      for (int ni=0; ni<4; ++ni){
        int nb = wn*32 + ni*8 + (lane>>2);
        bfv[ni][0] = Bw[nb*20 + kw];
        bfv[ni][1] = Bw[nb*20 + kw + 4];
      }
      #pragma unroll
      for (int mi=0; mi<4; ++mi)
        #pragma unroll
        for (int ni=0; ni<4; ++ni)
          mma16(acc[mi][ni], af[mi][0],af[mi][1],af[mi][2],af[mi][3],
                bfv[ni][0],bfv[ni][1]);
    }
    __syncthreads();
  }

  #pragma unroll
  for (int mi=0; mi<4; ++mi){
    #pragma unroll
    for (int ni=0; ni<4; ++ni){
      int r0 = m0 + wm*64 + mi*16 + (lane>>2);
      int c0 = n0 + wn*32 + ni*8 + ((lane&3)<<1);
      #pragma unroll
      for (int rr=0; rr<2; ++rr){
        int r = r0 + rr*8;
        #pragma unroll
        for (int cc=0; cc<2; ++cc){
          int c = c0 + cc;
          if (c >= N) continue;
          Cg[(size_t)r*N + c] = __float2bfloat16(acc[mi][ni][rr*2+cc]);
        }
      }
    }
  }
}

// ================= softmaxes (vectorized: 128 thr x 8 elems) =================
__device__ __forceinline__ float blk_max4(float x, float* red, int t){
  #pragma unroll
  for (int o=16;o;o>>=1) x = fmaxf(x, __shfl_xor_sync(0xffffffffu, x, o));
  if ((t&31)==0) red[t>>5] = x;
  __syncthreads();
  return fmaxf(fmaxf(red[0],red[1]), fmaxf(red[2],red[3]));
}
__device__ __forceinline__ float blk_sum4(float x, float* red, int t){
  #pragma unroll
  for (int o=16;o;o>>=1) x += __shfl_xor_sync(0xffffffffu, x, o);
  if ((t&31)==0) red[t>>5] = x;
  __syncthreads();
  return red[0]+red[1]+red[2]+red[3];
}

__global__ void __launch_bounds__(128) row_softmax1024_bf16(__nv_bfloat16* __restrict__ X){
  const size_t row = blockIdx.x;
  uint4* r4 = (uint4*)(X + (row << 10));
  const int t = threadIdx.x;
  __shared__ float red[4], red2[4];
  uint4 u = r4[t];
  uint32_t w[4] = {u.x,u.y,u.z,u.w};
  float v[8];
  #pragma unroll
  for (int j=0;j<4;j++){
    __nv_bfloat162 h = *reinterpret_cast<__nv_bfloat162*>(&w[j]);
    v[2*j]   = __low2float(h);
    v[2*j+1] = __high2float(h);
  }
  float mx = v[0];
  #pragma unroll
  for (int i=1;i<8;i++) mx = fmaxf(mx, v[i]);
  float m = blk_max4(mx, red, t);
  float s = 0.f;
  #pragma unroll
  for (int i=0;i<8;i++){ v[i] = __expf(v[i]-m); s += v[i]; }
  float S = blk_sum4(s, red2, t);
  float rc = 1.0f / S;
  #pragma unroll
  for (int j=0;j<4;j++){
    __nv_bfloat162 h = __floats2bfloat162_rn(v[2*j]*rc, v[2*j+1]*rc);
    w[j] = *reinterpret_cast<uint32_t*>(&h);
  }
  r4[t] = make_uint4(w[0],w[1],w[2],w[3]);
}

// bf16 logits -> fp32 probs
__global__ void __launch_bounds__(128) row_softmax1024_b2f(
    const __nv_bfloat16* __restrict__ X, float* __restrict__ Y){
  const size_t row = blockIdx.x;
  const uint4* r4 = (const uint4*)(X + (row << 10));
  float4* w4 = (float4*)(Y + (row << 10));
  const int t = threadIdx.x;
  __shared__ float red[4], red2[4];
  uint4 u = r4[t];
  uint32_t w[4] = {u.x,u.y,u.z,u.w};
  float v[8];
  #pragma unroll
  for (int j=0;j<4;j++){
    __nv_bfloat162 h = *reinterpret_cast<__nv_bfloat162*>(&w[j]);
    v[2*j]   = __low2float(h);
    v[2*j+1] = __high2float(h);
  }
  float mx = v[0];
  #pragma unroll
  for (int i=1;i<8;i++) mx = fmaxf(mx, v[i]);
  float m = blk_max4(mx, red, t);
  float s = 0.f;
  #pragma unroll
  for (int i=0;i<8;i++){ v[i] = __expf(v[i]-m); s += v[i]; }
  float S = blk_sum4(s, red2, t);
  float rc = 1.0f / S;
  w4[2*t]   = make_float4(v[0]*rc, v[1]*rc, v[2]*rc, v[3]*rc);
  w4[2*t+1] = make_float4(v[4]*rc, v[5]*rc, v[6]*rc, v[7]*rc);
}

extern "C" void kernel_launch(void* const* d_in, const int* in_sizes, int n_in,
                              void* d_out, int out_size){
  const float *l   =(const float*)d_in[0];
  const float *sp  =(const float*)d_in[1];
  const float *p   =(const float*)d_in[2];
  const float *Wq  =(const float*)d_in[3],  *bq  =(const float*)d_in[4];
  const float *Wksp=(const float*)d_in[5],  *bksp=(const float*)d_in[6];
  const float *Wkp =(const float*)d_in[7],  *bkp =(const float*)d_in[8];
  const float *Wvsp=(const float*)d_in[9],  *bvsp=(const float*)d_in[10];
  const float *Wo  =(const float*)d_in[13], *bo  =(const float*)d_in[14];
  float* out = (float*)d_out;

  __nv_bfloat16 *Q,*Ks,*Kp,*A1,*A2,*Mm;
  float *VT,*Mp,*O;
  cudaGetSymbolAddress((void**)&Q,  g_Qb);
  cudaGetSymbolAddress((void**)&Ks, g_Ksb);
  cudaGetSymbolAddress((void**)&Kp, g_Kpb);
  cudaGetSymbolAddress((void**)&VT, g_VT);
  cudaGetSymbolAddress((void**)&A1, g_A1b);
  cudaGetSymbolAddress((void**)&A2, g_A2b);
  cudaGetSymbolAddress((void**)&Mm, g_Mb);
  cudaGetSymbolAddress((void**)&Mp, g_Mp);
  cudaGetSymbolAddress((void**)&O,  g_O);

  const int SM128 = (2*TILEF + 2*128*LDSP)*4;  // 73728
  const int SM64  = (2*TILEF + 2*64*LDSP)*4;   // 55296
  cudaFuncSetAttribute((const void*)gemm_tn<128>,
                       cudaFuncAttributeMaxDynamicSharedMemorySize, SM128);
  cudaFuncSetAttribute((const void*)gemm_tn<64>,
                       cudaFuncAttributeMaxDynamicSharedMemorySize, SM64);
  cudaFuncSetAttribute((const void*)gemm_bf16_tn,
                       cudaFuncAttributeMaxDynamicSharedMemorySize, SMEMB2);

  const float sc = 0.125f;  // 64^-0.5
  dim3 th(256);

  // projections (tf32): Q/K bf16 head layout, V fp32 head-T (direct path)
  dim3 gp(8192/128, 768/128, 1);
  gemm_tn<128><<<gp, th, SM128>>>(l,  Wq,   bq,   Q,  8192,768,768, 0,0,0, sc, 4);
  gemm_tn<128><<<gp, th, SM128>>>(sp, Wksp, bksp, Ks, 8192,768,768, 0,0,0, sc, 4);
  gemm_tn<128><<<gp, th, SM128>>>(p,  Wkp,  bkp,  Kp, 8192,768,768, 0,0,0, sc, 4);
  gemm_tn<128><<<gp, th, SM128>>>(sp, Wvsp, bvsp, VT, 8192,768,768, 0,0,0, sc, 2);

  // logits transposed (bf16): A1T[k,s] = <Ksp[k,:],Q[s,:]>, A2T[p,s]
  dim3 gq(1024/128, 1024/128, 96);
  gemm_bf16_tn<<<gq, th, SMEMB2>>>(Ks, Q, A1, 1024,1024,64, 65536,65536,1048576);
  gemm_bf16_tn<<<gq, th, SMEMB2>>>(Kp, Q, A2, 1024,1024,64, 65536,65536,1048576);

  // softmax over s (rows of transposed maps), bf16 in/out
  row_softmax1024_bf16<<<96*1024, 128>>>(A1);
  row_softmax1024_bf16<<<96*1024, 128>>>(A2);

  // M[p,k] = sum_s A2T[p,s] * A1T[k,s]  (206 GFLOP, bf16)
  gemm_bf16_tn<<<gq, th, SMEMB2>>>(A2, A1, Mm, 1024,1024,1024,
                                   1048576,1048576,1048576);

  // softmax over k: bf16 logits -> fp32 probs
  row_softmax1024_b2f<<<96*1024, 128>>>(Mm, Mp);

  // O[p,d] = sum_k Mp[p,k] * VT[d,k]  (tf32 BN=64, fp32, merged heads)
  dim3 gv(1024/128, 1, 96);
  gemm_tn<64><<<gv, th, SM64>>>(Mp, VT, nullptr, O, 1024,64,1024,
                                1048576, 65536, 0, 1.f, 3);

  // final: out = O @ Wo^T + bo  (tf32, fp32 out)
  dim3 go(8192/128, 768/128, 1);
  gemm_tn<128><<<go, th, SM128>>>(O, Wo, bo, out, 8192,768,768, 0,0,0, 1.f, 0);
}